// round 13
// baseline (speedup 1.0000x reference)
#include <cuda_runtime.h>
#include <cstdint>

#define MUL0   64
#define MUL1   32
#define DIM    160
#define NPAIR0 2016
#define KTOT   2608
#define KPAD   2624
#define NCH    41          // 64-wide K chunks, phase 1
#define NCH2   16          // 64-wide N chunks, phase 2
#define TN     64          // nodes per CTA
#define THREADS 256        // 4 producer warps + 4 consumer warps

#define FSTR   68          // F row stride [n][k] (== 4 mod 32 -> conflict-free A frags + STS.128 gen stores)
#define WSTR   72          // weight/x0 row stride (== 8 mod 32 -> conflict-free B/A frags)
#define X1STR  64          // xs1 row stride (gen reads uniform-row, stride-free)

// ---------------- device scratch ----------------
__device__ float    g_WcB[NCH * 64 * WSTR];    // phase-1 B tiles [c][k][n], tf32, scaled
__device__ float    g_W3B[NCH2 * 64 * WSTR];   // phase-2 B tiles [ci][v][col], tf32, scaled
__device__ unsigned g_kmap[KPAD];              // k -> u | v<<8 | type<<16

// ---------------- helpers ----------------
__device__ __forceinline__ float to_tf32(float x) {
    uint32_t r; asm("cvt.rna.tf32.f32 %0, %1;" : "=r"(r) : "f"(x));
    return __uint_as_float(r);
}
__device__ __forceinline__ void cp_async16(uint32_t saddr, const void* gptr) {
    asm volatile("cp.async.cg.shared.global [%0], [%1], 16;\n" :: "r"(saddr), "l"(gptr));
}
__device__ __forceinline__ void cp_commit() { asm volatile("cp.async.commit_group;\n" ::: "memory"); }
__device__ __forceinline__ void cp_wait0() { asm volatile("cp.async.wait_group 0;\n" ::: "memory"); }
// consumer-group barrier (4 warps = 128 threads)
__device__ __forceinline__ void bar_cons() {
    asm volatile("bar.sync 1, 128;" ::: "memory");
}

__device__ __forceinline__ void mma_tf32(float* d, const uint32_t* a, const uint32_t* b) {
    asm volatile("mma.sync.aligned.m16n8k8.row.col.f32.tf32.tf32.f32 "
        "{%0,%1,%2,%3}, {%4,%5,%6,%7}, {%8,%9}, {%0,%1,%2,%3};"
        : "+f"(d[0]), "+f"(d[1]), "+f"(d[2]), "+f"(d[3])
        : "r"(a[0]), "r"(a[1]), "r"(a[2]), "r"(a[3]), "r"(b[0]), "r"(b[1]));
}
__device__ __forceinline__ uint32_t fbits(float x) { return __float_as_uint(x); }

// ---------------- prep: pack weights (tf32, scaled, strided) + pair table ----------------
__global__ void prep_kernel(const float* __restrict__ W1, const float* __restrict__ W2,
                            const float* __restrict__ W3, const float* __restrict__ W4,
                            const float* __restrict__ W5) {
    const float C0   = sqrtf(1.0f / 2608.0f);
    const float INV3 = 0.5773502691896258f;
    const float C0I  = C0 * INV3;
    const float C1I  = sqrtf(1.0f / 2048.0f);   // C1 * inv_sqrt3

    int t = blockIdx.x * blockDim.x + threadIdx.x;
    int stride = gridDim.x * blockDim.x;

    if (t < 64 * 64) {
        int u = t >> 6, v = t & 63;
        if (u < v)  g_kmap[u * 63 - (u * (u - 1)) / 2 + (v - u - 1)] = (unsigned)(u | (v << 8));
        if (u == v) g_kmap[NPAIR0 + u] = (unsigned)(u | (u << 8));
        if (u < 32 && v < 32) {
            if (u < v)  g_kmap[2080 + u * 31 - (u * (u - 1)) / 2 + (v - u - 1)] =
                            (unsigned)(u | (v << 8) | 0x10000);
            if (u == v) g_kmap[2576 + u] = (unsigned)(u | (u << 8) | 0x10000);
        }
    }
    if (t < KPAD - KTOT) g_kmap[KTOT + t] = 0u;

    // phase-1 B tiles: [c][k_local][n], n stride WSTR
    for (int idx = t; idx < NCH * 64 * WSTR; idx += stride) {
        int c = idx / (64 * WSTR);
        int rem = idx - c * 64 * WSTR;
        int kl = rem / WSTR, n = rem - kl * WSTR;
        float val = 0.f;
        if (n < 64) {
            int k = c * 64 + kl;
            if (k < NPAIR0)      val = C0  * W1[k * 64 + n];
            else if (k < 2080)   val = C0  * W2[(k - 2016) * 64 + n];
            else if (k < 2576)   val = C0I * W4[(k - 2080) * 64 + n];
            else if (k < KTOT)   val = C0I * W5[(k - 2576) * 64 + n];
            val = to_tf32(val);
        }
        g_WcB[idx] = val;
    }
    // phase-2 B tiles: [ci][v][col], col = ul*32 + w  (u = 2*ci + ul)
    for (int idx = t; idx < NCH2 * 64 * WSTR; idx += stride) {
        int ci = idx / (64 * WSTR);
        int rem = idx - ci * 64 * WSTR;
        int v = rem / WSTR, col = rem - v * WSTR;
        float val = 0.f;
        if (col < 64) {
            int u = 2 * ci + (col >> 5), w = col & 31;
            val = to_tf32(C1I * W3[(u * 64 + v) * 32 + w]);
        }
        g_W3B[idx] = val;
    }
}

// ---------------- smem layout (float indices), total 112KB -> 2 CTAs/SM ----------------
#define X0_OFF  0                          // x0  [64 d][72]  = 4608 (tf32; gen + phase-2 A)
#define X1_OFF  4608                       // xs1 [96][64]    = 6144 (fp32; gen + contraction)
#define F_OFF   10752                      // F/Y double buffer: 2 x 64x68 = 8704
#define W_OFF   19456                      // W double buffer: 2 x 64x72 = 9216
#define SMEM_FLOATS 28672
#define SMEM_BYTES  (SMEM_FLOATS * 4)      // 114688 B = 112 KB

#define WCHUNK_FLOATS (64 * WSTR)          // 4608
#define FBUF_FLOATS   (64 * FSTR)          // 4352

__global__ void __launch_bounds__(THREADS, 2)
node_block_kernel(const float* __restrict__ A, const float* __restrict__ B,
                  float* __restrict__ out, int nNodes) {
    extern __shared__ float sm[];
    float* x0   = sm + X0_OFF;
    float* xs1  = sm + X1_OFF;
    float* Fbuf = sm + F_OFF;
    float* Wbuf = sm + W_OFF;

    const int t    = threadIdx.x;
    const int lane = t & 31;
    const int warp = t >> 5;
    const bool prod = (warp < 4);       // producers: gen / contraction
    const int cw   = warp - 4;          // consumer warp 0..3
    const int rg   = (cw >> 1) & 1;     // row group (32 rows)
    const int cg   = cw & 1;            // col group (32 cols)
    const int gy   = lane >> 2;
    const int gx   = lane & 3;
    const int nbase = blockIdx.x * TN;
    const uint32_t w_s = (uint32_t)__cvta_generic_to_shared(Wbuf);
    const int tc = t & 127;             // index within group

    // consumers prefetch Wc chunk 0 into W[0]
    if (!prod) {
        const char* src = (const char*)&g_WcB[0];
        #pragma unroll
        for (int j = 0; j < 9; ++j) {
            int e = tc + 128 * j;
            if (e < WCHUNK_FLOATS / 4) cp_async16(w_s + e * 16, src + e * 16);
        }
        cp_commit();
    }

    // all threads: load x = A + B
    for (int e = t; e < TN * DIM; e += THREADS) {
        int n = e / DIM, d = e - n * DIM;
        int gn = nbase + n;
        float v = 0.f;
        if (gn < nNodes) v = A[(size_t)gn * DIM + d] + B[(size_t)gn * DIM + d];
        if (d < MUL0) {
            x0[d * WSTR + n] = to_tf32(v);
        } else {
            int dd = d - MUL0; int u = dd / 3, i = dd - 3 * u;
            xs1[(i * MUL1 + u) * X1STR + n] = v;
        }
    }
    __syncthreads();

    // ================= phase 1: out0 = F(x) @ WcT (producer/consumer pipeline) ========
    float d1[2][4][4];
    if (!prod) {
        #pragma unroll
        for (int mt = 0; mt < 2; ++mt)
            #pragma unroll
            for (int nt = 0; nt < 4; ++nt)
                #pragma unroll
                for (int p = 0; p < 4; ++p) d1[mt][nt][p] = 0.f;
    }

    // ---- gen: chunk cc into buffer bb ----
    #define GEN_CHUNK(cc, bb) do {                                                      \
        const unsigned* kmp = &g_kmap[(cc) * 64];                                       \
        float* Fb = Fbuf + (bb) * FBUF_FLOATS;                                          \
        _Pragma("unroll")                                                               \
        for (int j = 0; j < 8; ++j) {                                                   \
            int wt = j * 4 + warp;                                                      \
            int kq = wt & 15;                                                           \
            int n  = (wt >> 4) * 32 + lane;                                             \
            float4 val;                                                                 \
            float* vp = &val.x;                                                         \
            _Pragma("unroll")                                                           \
            for (int q = 0; q < 4; ++q) {                                               \
                unsigned km = kmp[kq * 4 + q];                                          \
                int u = km & 255, v = (km >> 8) & 255;                                  \
                float r;                                                                \
                if (km & 0x10000u)                                                      \
                    r = xs1[u * X1STR + n] * xs1[v * X1STR + n]                         \
                      + xs1[(32 + u) * X1STR + n] * xs1[(32 + v) * X1STR + n]           \
                      + xs1[(64 + u) * X1STR + n] * xs1[(64 + v) * X1STR + n];          \
                else                                                                    \
                    r = x0[u * WSTR + n] * x0[v * WSTR + n];                            \
                vp[q] = to_tf32(r);                                                     \
            }                                                                           \
            *(float4*)&Fb[n * FSTR + kq * 4] = val;                                     \
        }                                                                               \
    } while (0)

    if (prod) GEN_CHUNK(0, 0);
    __syncthreads();

    for (int c = 0; c < NCH; ++c) {
        if (prod) {
            if (c + 1 < NCH) GEN_CHUNK(c + 1, (c + 1) & 1);
        } else {
            // ---- consumers: mma chunk c ----
            const float* Fb = Fbuf + (c & 1) * FBUF_FLOATS;
            const float* Wb = Wbuf + (c & 1) * WCHUNK_FLOATS;
            cp_wait0();    // own copies landed
            bar_cons();    // cross-consumer visibility
            #pragma unroll 2
            for (int ks = 0; ks < 8; ++ks) {
                const int k0 = 8 * ks;
                uint32_t a[2][4], bf[4][2];
                #pragma unroll
                for (int mt = 0; mt < 2; ++mt) {
                    int base = (32 * rg + 16 * mt + gy) * FSTR + k0 + gx;
                    a[mt][0] = fbits(Fb[base]);
                    a[mt][1] = fbits(Fb[base + 8 * FSTR]);
                    a[mt][2] = fbits(Fb[base + 4]);
                    a[mt][3] = fbits(Fb[base + 8 * FSTR + 4]);
                }
                #pragma unroll
                for (int nt = 0; nt < 4; ++nt) {
                    int bbase = (k0 + gx) * WSTR + 32 * cg + 8 * nt + gy;
                    bf[nt][0] = fbits(Wb[bbase]);
                    bf[nt][1] = fbits(Wb[bbase + 4 * WSTR]);
                }
                #pragma unroll
                for (int mt = 0; mt < 2; ++mt)
                    #pragma unroll
                    for (int nt = 0; nt < 4; ++nt)
                        mma_tf32(d1[mt][nt], a[mt], bf[nt]);
            }
            // prefetch weight chunk c+1
            if (c + 1 < NCH) {
                const char* src = (const char*)&g_WcB[(c + 1) * WCHUNK_FLOATS];
                uint32_t dst = w_s + ((c + 1) & 1) * WCHUNK_FLOATS * 4;
                #pragma unroll
                for (int j = 0; j < 9; ++j) {
                    int e = tc + 128 * j;
                    if (e < WCHUNK_FLOATS / 4) cp_async16(dst + e * 16, src + e * 16);
                }
                cp_commit();
            }
        }
        __syncthreads();
    }

    // ---- phase-1 epilogue (consumers): store out0; prefetch W3[0] ----
    if (!prod) {
        #pragma unroll
        for (int mt = 0; mt < 2; ++mt) {
            #pragma unroll
            for (int nt = 0; nt < 4; ++nt) {
                int r = 32 * rg + 16 * mt + gy;
                int cc = 32 * cg + 8 * nt + 2 * gx;
                int gn = nbase + r;
                if (gn < nNodes)
                    *(float2*)&out[(size_t)gn * DIM + cc] = make_float2(d1[mt][nt][0], d1[mt][nt][1]);
                int gn2 = nbase + r + 8;
                if (gn2 < nNodes)
                    *(float2*)&out[(size_t)gn2 * DIM + cc] = make_float2(d1[mt][nt][2], d1[mt][nt][3]);
            }
        }
        const char* src = (const char*)&g_W3B[0];
        #pragma unroll
        for (int j = 0; j < 9; ++j) {
            int e = tc + 128 * j;
            if (e < WCHUNK_FLOATS / 4) cp_async16(w_s + e * 16, src + e * 16);
        }
        cp_commit();
    }

    // ================= phase 2: Y = x0 @ W3r; producers contract =================
    const int n2 = tc >> 1;    // producer node 0..63
    const int h  = tc & 1;     // w half
    float o[48];
    #pragma unroll
    for (int j = 0; j < 48; ++j) o[j] = 0.f;

    for (int ci = 0; ci < NCH2; ++ci) {
        if (!prod) {
            float* Yb = Fbuf + (ci & 1) * FBUF_FLOATS;
            const float* Wb = Wbuf + (ci & 1) * WCHUNK_FLOATS;
            cp_wait0();
            bar_cons();

            float d2[2][4][4];
            #pragma unroll
            for (int mt = 0; mt < 2; ++mt)
                #pragma unroll
                for (int nt = 0; nt < 4; ++nt)
                    #pragma unroll
                    for (int p = 0; p < 4; ++p) d2[mt][nt][p] = 0.f;

            #pragma unroll 2
            for (int ks = 0; ks < 8; ++ks) {
                const int k0 = 8 * ks;
                uint32_t a[2][4], bf[4][2];
                #pragma unroll
                for (int mt = 0; mt < 2; ++mt) {
                    // A = x0: [v][n] layout, rows v (K), node = M index
                    int node = 32 * rg + 16 * mt + gy;
                    a[mt][0] = fbits(x0[(k0 + gx) * WSTR + node]);
                    a[mt][1] = fbits(x0[(k0 + gx) * WSTR + node + 8]);
                    a[mt][2] = fbits(x0[(k0 + gx + 4) * WSTR + node]);
                    a[mt][3] = fbits(x0[(k0 + gx + 4) * WSTR + node + 8]);
                }
                #pragma unroll
                for (int nt = 0; nt < 4; ++nt) {
                    int bbase = (k0 + gx) * WSTR + 32 * cg + 8 * nt + gy;
                    bf[nt][0] = fbits(Wb[bbase]);
                    bf[nt][1] = fbits(Wb[bbase + 4 * WSTR]);
                }
                #pragma unroll
                for (int mt = 0; mt < 2; ++mt)
                    #pragma unroll
                    for (int nt = 0; nt < 4; ++nt)
                        mma_tf32(d2[mt][nt], a[mt], bf[nt]);
            }

            // store Y fragments into Yb [n][68]
            #pragma unroll
            for (int mt = 0; mt < 2; ++mt) {
                #pragma unroll
                for (int nt = 0; nt < 4; ++nt) {
                    int r = 32 * rg + 16 * mt + gy;
                    int cc = 32 * cg + 8 * nt + 2 * gx;
                    *(float2*)&Yb[r * FSTR + cc]       = make_float2(d2[mt][nt][0], d2[mt][nt][1]);
                    *(float2*)&Yb[(r + 8) * FSTR + cc] = make_float2(d2[mt][nt][2], d2[mt][nt][3]);
                }
            }

            if (ci + 1 < NCH2) {
                const char* src = (const char*)&g_W3B[(ci + 1) * WCHUNK_FLOATS];
                uint32_t dst = w_s + ((ci + 1) & 1) * WCHUNK_FLOATS * 4;
                #pragma unroll
                for (int j = 0; j < 9; ++j) {
                    int e = tc + 128 * j;
                    if (e < WCHUNK_FLOATS / 4) cp_async16(dst + e * 16, src + e * 16);
                }
                cp_commit();
            }
        } else if (ci > 0) {
            // producers: contract Y chunk ci-1
            const float* Yb = Fbuf + ((ci - 1) & 1) * FBUF_FLOATS;
            #pragma unroll
            for (int ul = 0; ul < 2; ++ul) {
                int u = 2 * (ci - 1) + ul;
                float xi0 = xs1[(0 * MUL1 + u) * X1STR + n2];
                float xi1 = xs1[(1 * MUL1 + u) * X1STR + n2];
                float xi2 = xs1[(2 * MUL1 + u) * X1STR + n2];
                #pragma unroll
                for (int q = 0; q < 4; ++q) {
                    float4 y = *(const float4*)&Yb[n2 * FSTR + ul * 32 + 16 * h + 4 * q];
                    float yv[4] = {y.x, y.y, y.z, y.w};
                    #pragma unroll
                    for (int e = 0; e < 4; ++e) {
                        int lw = 4 * q + e;
                        o[lw * 3 + 0] += yv[e] * xi0;
                        o[lw * 3 + 1] += yv[e] * xi1;
                        o[lw * 3 + 2] += yv[e] * xi2;
                    }
                }
            }
        }
        __syncthreads();
    }

    // final contraction (chunk 15) + out1 store, producers only
    if (prod) {
        const float* Yb = Fbuf + ((NCH2 - 1) & 1) * FBUF_FLOATS;
        #pragma unroll
        for (int ul = 0; ul < 2; ++ul) {
            int u = 2 * (NCH2 - 1) + ul;
            float xi0 = xs1[(0 * MUL1 + u) * X1STR + n2];
            float xi1 = xs1[(1 * MUL1 + u) * X1STR + n2];
            float xi2 = xs1[(2 * MUL1 + u) * X1STR + n2];
            #pragma unroll
            for (int q = 0; q < 4; ++q) {
                float4 y = *(const float4*)&Yb[n2 * FSTR + ul * 32 + 16 * h + 4 * q];
                float yv[4] = {y.x, y.y, y.z, y.w};
                #pragma unroll
                for (int e = 0; e < 4; ++e) {
                    int lw = 4 * q + e;
                    o[lw * 3 + 0] += yv[e] * xi0;
                    o[lw * 3 + 1] += yv[e] * xi1;
                    o[lw * 3 + 2] += yv[e] * xi2;
                }
            }
        }
        int gn = nbase + n2;
        if (gn < nNodes) {
            float* dst = &out[(size_t)gn * DIM + MUL0 + 48 * h];
            #pragma unroll
            for (int j = 0; j < 12; ++j)
                *(float4*)&dst[4 * j] = make_float4(o[4 * j], o[4 * j + 1], o[4 * j + 2], o[4 * j + 3]);
        }
    }
}

// ---------------- launch ----------------
extern "C" void kernel_launch(void* const* d_in, const int* in_sizes, int n_in,
                              void* d_out, int out_size) {
    const float* A  = (const float*)d_in[0];
    const float* B  = (const float*)d_in[1];
    const float* W1 = (const float*)d_in[2];
    const float* W2 = (const float*)d_in[3];
    const float* W3 = (const float*)d_in[4];
    const float* W4 = (const float*)d_in[5];
    const float* W5 = (const float*)d_in[6];
    float* out = (float*)d_out;
    int nNodes = in_sizes[0] / DIM;

    cudaFuncSetAttribute(node_block_kernel,
                         cudaFuncAttributeMaxDynamicSharedMemorySize, SMEM_BYTES);

    prep_kernel<<<256, 256>>>(W1, W2, W3, W4, W5);
    int nb = (nNodes + TN - 1) / TN;
    node_block_kernel<<<nb, THREADS, SMEM_BYTES>>>(A, B, out, nNodes);
}

// round 14
// speedup vs baseline: 1.3357x; 1.3357x over previous
#include <cuda_runtime.h>
#include <cstdint>

#define MUL0   64
#define MUL1   32
#define DIM    160
#define NPAIR0 2016
#define KTOT   2608
#define KPAD   2624
#define NCH    41          // 64-wide K chunks, phase 1
#define NCH2   16          // 64-wide N chunks, phase 2
#define TN     128
#define THREADS 512        // 12 producer warps + 4 consumer warps

#define FSTR   68          // F / x0r row stride (== 4 mod 32 -> conflict-free A frags)
#define WSTR   72          // weight tile row stride (== 8 mod 32 -> conflict-free B frags)
#define XSTR   132         // xs0l/xs1l row stride

// ---------------- device scratch ----------------
__device__ float    g_WcB[NCH * 64 * WSTR];    // phase-1 B tiles [c][k][n], tf32, scaled
__device__ float    g_W3B[NCH2 * 64 * WSTR];   // phase-2 B tiles [ci][v][col], tf32, scaled
__device__ unsigned g_kmap[KPAD];              // k -> u | v<<8 | type<<16

// ---------------- helpers ----------------
__device__ __forceinline__ float to_tf32(float x) {
    uint32_t r; asm("cvt.rna.tf32.f32 %0, %1;" : "=r"(r) : "f"(x));
    return __uint_as_float(r);
}
__device__ __forceinline__ void cp_async16(uint32_t saddr, const void* gptr) {
    asm volatile("cp.async.cg.shared.global [%0], [%1], 16;\n" :: "r"(saddr), "l"(gptr));
}
__device__ __forceinline__ void cp_commit() { asm volatile("cp.async.commit_group;\n" ::: "memory"); }
__device__ __forceinline__ void cp_wait0() { asm volatile("cp.async.wait_group 0;\n" ::: "memory"); }
// consumer-group barrier (4 warps = 128 threads)
__device__ __forceinline__ void bar_cons() {
    asm volatile("bar.sync 1, 128;" ::: "memory");
}

__device__ __forceinline__ void mma_tf32(float* d, const uint32_t* a, const uint32_t* b) {
    asm volatile("mma.sync.aligned.m16n8k8.row.col.f32.tf32.tf32.f32 "
        "{%0,%1,%2,%3}, {%4,%5,%6,%7}, {%8,%9}, {%0,%1,%2,%3};"
        : "+f"(d[0]), "+f"(d[1]), "+f"(d[2]), "+f"(d[3])
        : "r"(a[0]), "r"(a[1]), "r"(a[2]), "r"(a[3]), "r"(b[0]), "r"(b[1]));
}
__device__ __forceinline__ uint32_t fbits(float x) { return __float_as_uint(x); }

// ---------------- prep: pack weights (tf32, scaled, strided) + pair table ----------------
__global__ void prep_kernel(const float* __restrict__ W1, const float* __restrict__ W2,
                            const float* __restrict__ W3, const float* __restrict__ W4,
                            const float* __restrict__ W5) {
    const float C0   = sqrtf(1.0f / 2608.0f);
    const float INV3 = 0.5773502691896258f;
    const float C0I  = C0 * INV3;
    const float C1I  = sqrtf(1.0f / 2048.0f);   // C1 * inv_sqrt3

    int t = blockIdx.x * blockDim.x + threadIdx.x;
    int stride = gridDim.x * blockDim.x;

    if (t < 64 * 64) {
        int u = t >> 6, v = t & 63;
        if (u < v)  g_kmap[u * 63 - (u * (u - 1)) / 2 + (v - u - 1)] = (unsigned)(u | (v << 8));
        if (u == v) g_kmap[NPAIR0 + u] = (unsigned)(u | (u << 8));
        if (u < 32 && v < 32) {
            if (u < v)  g_kmap[2080 + u * 31 - (u * (u - 1)) / 2 + (v - u - 1)] =
                            (unsigned)(u | (v << 8) | 0x10000);
            if (u == v) g_kmap[2576 + u] = (unsigned)(u | (u << 8) | 0x10000);
        }
    }
    if (t < KPAD - KTOT) g_kmap[KTOT + t] = 0u;

    // phase-1 B tiles: [c][k_local][n], n stride WSTR
    for (int idx = t; idx < NCH * 64 * WSTR; idx += stride) {
        int c = idx / (64 * WSTR);
        int rem = idx - c * 64 * WSTR;
        int kl = rem / WSTR, n = rem - kl * WSTR;
        float val = 0.f;
        if (n < 64) {
            int k = c * 64 + kl;
            if (k < NPAIR0)      val = C0  * W1[k * 64 + n];
            else if (k < 2080)   val = C0  * W2[(k - 2016) * 64 + n];
            else if (k < 2576)   val = C0I * W4[(k - 2080) * 64 + n];
            else if (k < KTOT)   val = C0I * W5[(k - 2576) * 64 + n];
            val = to_tf32(val);
        }
        g_WcB[idx] = val;
    }
    // phase-2 B tiles: [ci][v][col], col = ul*32 + w  (u = 2*ci + ul)
    for (int idx = t; idx < NCH2 * 64 * WSTR; idx += stride) {
        int ci = idx / (64 * WSTR);
        int rem = idx - ci * 64 * WSTR;
        int v = rem / WSTR, col = rem - v * WSTR;
        float val = 0.f;
        if (col < 64) {
            int u = 2 * ci + (col >> 5), w = col & 31;
            val = to_tf32(C1I * W3[(u * 64 + v) * 32 + w]);
        }
        g_W3B[idx] = val;
    }
}

// ---------------- smem layout (float indices) ----------------
#define XS0L_OFF 0                          // xs0l [64][132]  = 8448
#define XS1L_OFF 8448                       // xs1l [96][132]  = 12672
#define X0R_OFF  21120                      // x0r  [128][68]  = 8704 (tf32)
#define F_OFF    29824                      // F/Y double buffer: 2 x 128x68 = 17408
#define W_OFF    47232                      // W double buffer: 2 x 64x72 = 9216
#define SMEM_FLOATS 56448
#define SMEM_BYTES  (SMEM_FLOATS * 4)       // 225792 B

#define WCHUNK_FLOATS (64 * WSTR)           // 4608
#define FBUF_FLOATS   (128 * FSTR)          // 8704

__global__ void __launch_bounds__(THREADS)
node_block_kernel(const float* __restrict__ A, const float* __restrict__ B,
                  float* __restrict__ out, int nNodes) {
    extern __shared__ float sm[];
    float* xs0l = sm + XS0L_OFF;
    float* xs1l = sm + XS1L_OFF;
    float* x0r  = sm + X0R_OFF;
    float* Fbuf = sm + F_OFF;
    float* Wbuf = sm + W_OFF;

    const int t    = threadIdx.x;
    const int lane = t & 31;
    const int warp = t >> 5;
    const bool prod = (warp < 12);      // producers: gen / contraction
    const int cw   = warp - 12;         // consumer warp 0..3
    const int rg   = (cw >> 1) & 1;     // row group (64 rows)
    const int cg   = cw & 1;            // col group (32 cols)
    const int gy   = lane >> 2;
    const int gx   = lane & 3;
    const int nbase = blockIdx.x * TN;
    const uint32_t w_s = (uint32_t)__cvta_generic_to_shared(Wbuf);
    const int tcc = t - 384;            // consumer-local index (0..127 for consumers)

    // consumers prefetch Wc chunk 0 into W[0]
    if (!prod) {
        const char* src = (const char*)&g_WcB[0];
        #pragma unroll
        for (int j = 0; j < 9; ++j) {
            int e = tcc + 128 * j;
            if (e < WCHUNK_FLOATS / 4) cp_async16(w_s + e * 16, src + e * 16);
        }
        cp_commit();
    }

    // all threads: load x = A + B into xs0l, xs1l (fp32) and x0r (tf32)
    for (int e = t; e < TN * DIM; e += THREADS) {
        int n = e / DIM, d = e - n * DIM;
        int gn = nbase + n;
        float v = 0.f;
        if (gn < nNodes) v = A[(size_t)gn * DIM + d] + B[(size_t)gn * DIM + d];
        if (d < MUL0) {
            xs0l[d * XSTR + n] = v;
            x0r[n * FSTR + d] = to_tf32(v);
        } else {
            int dd = d - MUL0; int u = dd / 3, i = dd - 3 * u;
            xs1l[(i * MUL1 + u) * XSTR + n] = v;
        }
    }
    __syncthreads();

    // ================= phase 1: out0 = F(x) @ WcT (producer/consumer pipeline) ========
    float d1[4][4][4];
    if (!prod) {
        #pragma unroll
        for (int mt = 0; mt < 4; ++mt)
            #pragma unroll
            for (int nt = 0; nt < 4; ++nt)
                #pragma unroll
                for (int p = 0; p < 4; ++p) d1[mt][nt][p] = 0.f;
    }

    // ---- gen: chunk cc into buffer bb (12 warps, 64 tasks round-robin) ----
    #define GEN_CHUNK(cc, bb) do {                                                          \
        const unsigned* kmp = &g_kmap[(cc) * 64];                                           \
        float* Fb = Fbuf + (bb) * FBUF_FLOATS;                                              \
        for (int task = warp; task < 64; task += 12) {                                      \
            int k  = lane + 32 * (task & 1);                                                \
            int n4 = 4 * (task >> 1);                                                       \
            unsigned km = kmp[k];                                                           \
            int u = km & 255, v = (km >> 8) & 255;                                          \
            float4 val;                                                                     \
            if (km & 0x10000u) {                                                            \
                const float4 a0 = *(const float4*)&xs1l[(0 * MUL1 + u) * XSTR + n4];        \
                const float4 b0 = *(const float4*)&xs1l[(0 * MUL1 + v) * XSTR + n4];        \
                const float4 a1 = *(const float4*)&xs1l[(1 * MUL1 + u) * XSTR + n4];        \
                const float4 b1 = *(const float4*)&xs1l[(1 * MUL1 + v) * XSTR + n4];        \
                const float4 a2 = *(const float4*)&xs1l[(2 * MUL1 + u) * XSTR + n4];        \
                const float4 b2 = *(const float4*)&xs1l[(2 * MUL1 + v) * XSTR + n4];        \
                val.x = a0.x * b0.x + a1.x * b1.x + a2.x * b2.x;                            \
                val.y = a0.y * b0.y + a1.y * b1.y + a2.y * b2.y;                            \
                val.z = a0.z * b0.z + a1.z * b1.z + a2.z * b2.z;                            \
                val.w = a0.w * b0.w + a1.w * b1.w + a2.w * b2.w;                            \
            } else {                                                                        \
                const float4 a = *(const float4*)&xs0l[u * XSTR + n4];                      \
                const float4 bb2 = *(const float4*)&xs0l[v * XSTR + n4];                    \
                val.x = a.x * bb2.x; val.y = a.y * bb2.y;                                   \
                val.z = a.z * bb2.z; val.w = a.w * bb2.w;                                   \
            }                                                                               \
            Fb[(n4 + 0) * FSTR + k] = to_tf32(val.x);                                       \
            Fb[(n4 + 1) * FSTR + k] = to_tf32(val.y);                                       \
            Fb[(n4 + 2) * FSTR + k] = to_tf32(val.z);                                       \
            Fb[(n4 + 3) * FSTR + k] = to_tf32(val.w);                                       \
        }                                                                                   \
    } while (0)

    if (prod) GEN_CHUNK(0, 0);
    __syncthreads();

    for (int c = 0; c < NCH; ++c) {
        if (prod) {
            if (c + 1 < NCH) GEN_CHUNK(c + 1, (c + 1) & 1);
        } else {
            // ---- consumers: mma chunk c, 64x32 warp tile ----
            const float* Fb = Fbuf + (c & 1) * FBUF_FLOATS;
            const float* Wb = Wbuf + (c & 1) * WCHUNK_FLOATS;
            cp_wait0();    // own copies landed
            bar_cons();    // cross-consumer visibility
            #pragma unroll 2
            for (int ks = 0; ks < 8; ++ks) {
                const int k0 = 8 * ks;
                uint32_t a[4][4], bf[4][2];
                #pragma unroll
                for (int mt = 0; mt < 4; ++mt) {
                    int base = (64 * rg + 16 * mt + gy) * FSTR + k0 + gx;
                    a[mt][0] = fbits(Fb[base]);
                    a[mt][1] = fbits(Fb[base + 8 * FSTR]);
                    a[mt][2] = fbits(Fb[base + 4]);
                    a[mt][3] = fbits(Fb[base + 8 * FSTR + 4]);
                }
                #pragma unroll
                for (int nt = 0; nt < 4; ++nt) {
                    int bbase = (k0 + gx) * WSTR + 32 * cg + 8 * nt + gy;
                    bf[nt][0] = fbits(Wb[bbase]);
                    bf[nt][1] = fbits(Wb[bbase + 4 * WSTR]);
                }
                #pragma unroll
                for (int mt = 0; mt < 4; ++mt)
                    #pragma unroll
                    for (int nt = 0; nt < 4; ++nt)
                        mma_tf32(d1[mt][nt], a[mt], bf[nt]);
            }
            // prefetch weight chunk c+1
            if (c + 1 < NCH) {
                const char* src = (const char*)&g_WcB[(c + 1) * WCHUNK_FLOATS];
                uint32_t dst = w_s + ((c + 1) & 1) * WCHUNK_FLOATS * 4;
                #pragma unroll
                for (int j = 0; j < 9; ++j) {
                    int e = tcc + 128 * j;
                    if (e < WCHUNK_FLOATS / 4) cp_async16(dst + e * 16, src + e * 16);
                }
                cp_commit();
            }
        }
        __syncthreads();
    }

    // ---- phase-1 epilogue (consumers): store out0; then prefetch W3[0] ----
    if (!prod) {
        #pragma unroll
        for (int mt = 0; mt < 4; ++mt) {
            #pragma unroll
            for (int nt = 0; nt < 4; ++nt) {
                int r = 64 * rg + 16 * mt + gy;
                int cc = 32 * cg + 8 * nt + 2 * gx;
                int gn = nbase + r;
                if (gn < nNodes)
                    *(float2*)&out[(size_t)gn * DIM + cc] = make_float2(d1[mt][nt][0], d1[mt][nt][1]);
                int gn2 = nbase + r + 8;
                if (gn2 < nNodes)
                    *(float2*)&out[(size_t)gn2 * DIM + cc] = make_float2(d1[mt][nt][2], d1[mt][nt][3]);
            }
        }
        const char* src = (const char*)&g_W3B[0];
        #pragma unroll
        for (int j = 0; j < 9; ++j) {
            int e = tcc + 128 * j;
            if (e < WCHUNK_FLOATS / 4) cp_async16(w_s + e * 16, src + e * 16);
        }
        cp_commit();
    }

    // ================= phase 2: Y = x0 @ W3r; producers contract =================
    const int n2 = t >> 1;     // producer node (valid for t < 256)
    const int h  = t & 1;      // w half
    float o[48];
    #pragma unroll
    for (int j = 0; j < 48; ++j) o[j] = 0.f;

    for (int ci = 0; ci < NCH2; ++ci) {
        if (!prod) {
            float* Yb = Fbuf + (ci & 1) * FBUF_FLOATS;
            const float* Wb = Wbuf + (ci & 1) * WCHUNK_FLOATS;
            cp_wait0();
            bar_cons();

            float d2[4][4][4];
            #pragma unroll
            for (int mt = 0; mt < 4; ++mt)
                #pragma unroll
                for (int nt = 0; nt < 4; ++nt)
                    #pragma unroll
                    for (int p = 0; p < 4; ++p) d2[mt][nt][p] = 0.f;

            #pragma unroll 2
            for (int ks = 0; ks < 8; ++ks) {
                const int k0 = 8 * ks;
                uint32_t a[4][4], bf[4][2];
                #pragma unroll
                for (int mt = 0; mt < 4; ++mt) {
                    int base = (64 * rg + 16 * mt + gy) * FSTR + k0 + gx;
                    a[mt][0] = fbits(x0r[base]);
                    a[mt][1] = fbits(x0r[base + 8 * FSTR]);
                    a[mt][2] = fbits(x0r[base + 4]);
                    a[mt][3] = fbits(x0r[base + 8 * FSTR + 4]);
                }
                #pragma unroll
                for (int nt = 0; nt < 4; ++nt) {
                    int bbase = (k0 + gx) * WSTR + 32 * cg + 8 * nt + gy;
                    bf[nt][0] = fbits(Wb[bbase]);
                    bf[nt][1] = fbits(Wb[bbase + 4 * WSTR]);
                }
                #pragma unroll
                for (int mt = 0; mt < 4; ++mt)
                    #pragma unroll
                    for (int nt = 0; nt < 4; ++nt)
                        mma_tf32(d2[mt][nt], a[mt], bf[nt]);
            }

            // store Y fragments
            #pragma unroll
            for (int mt = 0; mt < 4; ++mt) {
                #pragma unroll
                for (int nt = 0; nt < 4; ++nt) {
                    int r = 64 * rg + 16 * mt + gy;
                    int cc = 32 * cg + 8 * nt + 2 * gx;
                    *(float2*)&Yb[r * FSTR + cc]       = make_float2(d2[mt][nt][0], d2[mt][nt][1]);
                    *(float2*)&Yb[(r + 8) * FSTR + cc] = make_float2(d2[mt][nt][2], d2[mt][nt][3]);
                }
            }

            if (ci + 1 < NCH2) {
                const char* src = (const char*)&g_W3B[(ci + 1) * WCHUNK_FLOATS];
                uint32_t dst = w_s + ((ci + 1) & 1) * WCHUNK_FLOATS * 4;
                #pragma unroll
                for (int j = 0; j < 9; ++j) {
                    int e = tcc + 128 * j;
                    if (e < WCHUNK_FLOATS / 4) cp_async16(dst + e * 16, src + e * 16);
                }
                cp_commit();
            }
        } else if (ci > 0 && t < 256) {
            // producers: contract Y chunk ci-1
            const float* Yb = Fbuf + ((ci - 1) & 1) * FBUF_FLOATS;
            #pragma unroll
            for (int ul = 0; ul < 2; ++ul) {
                int u = 2 * (ci - 1) + ul;
                float xi0 = xs1l[(0 * MUL1 + u) * XSTR + n2];
                float xi1 = xs1l[(1 * MUL1 + u) * XSTR + n2];
                float xi2 = xs1l[(2 * MUL1 + u) * XSTR + n2];
                #pragma unroll
                for (int q = 0; q < 4; ++q) {
                    float4 y = *(const float4*)&Yb[n2 * FSTR + ul * 32 + 16 * h + 4 * q];
                    float yv[4] = {y.x, y.y, y.z, y.w};
                    #pragma unroll
                    for (int e = 0; e < 4; ++e) {
                        int lw = 4 * q + e;
                        o[lw * 3 + 0] += yv[e] * xi0;
                        o[lw * 3 + 1] += yv[e] * xi1;
                        o[lw * 3 + 2] += yv[e] * xi2;
                    }
                }
            }
        }
        __syncthreads();
    }

    // final contraction (chunk 15) + out1 store, producer threads t<256 only
    if (prod && t < 256) {
        const float* Yb = Fbuf + ((NCH2 - 1) & 1) * FBUF_FLOATS;
        #pragma unroll
        for (int ul = 0; ul < 2; ++ul) {
            int u = 2 * (NCH2 - 1) + ul;
            float xi0 = xs1l[(0 * MUL1 + u) * XSTR + n2];
            float xi1 = xs1l[(1 * MUL1 + u) * XSTR + n2];
            float xi2 = xs1l[(2 * MUL1 + u) * XSTR + n2];
            #pragma unroll
            for (int q = 0; q < 4; ++q) {
                float4 y = *(const float4*)&Yb[n2 * FSTR + ul * 32 + 16 * h + 4 * q];
                float yv[4] = {y.x, y.y, y.z, y.w};
                #pragma unroll
                for (int e = 0; e < 4; ++e) {
                    int lw = 4 * q + e;
                    o[lw * 3 + 0] += yv[e] * xi0;
                    o[lw * 3 + 1] += yv[e] * xi1;
                    o[lw * 3 + 2] += yv[e] * xi2;
                }
            }
        }
        int gn = nbase + n2;
        if (gn < nNodes) {
            float* dst = &out[(size_t)gn * DIM + MUL0 + 48 * h];
            #pragma unroll
            for (int j = 0; j < 12; ++j)
                *(float4*)&dst[4 * j] = make_float4(o[4 * j], o[4 * j + 1], o[4 * j + 2], o[4 * j + 3]);
        }
    }
}

// ---------------- launch ----------------
extern "C" void kernel_launch(void* const* d_in, const int* in_sizes, int n_in,
                              void* d_out, int out_size) {
    const float* A  = (const float*)d_in[0];
    const float* B  = (const float*)d_in[1];
    const float* W1 = (const float*)d_in[2];
    const float* W2 = (const float*)d_in[3];
    const float* W3 = (const float*)d_in[4];
    const float* W4 = (const float*)d_in[5];
    const float* W5 = (const float*)d_in[6];
    float* out = (float*)d_out;
    int nNodes = in_sizes[0] / DIM;

    cudaFuncSetAttribute(node_block_kernel,
                         cudaFuncAttributeMaxDynamicSharedMemorySize, SMEM_BYTES);

    prep_kernel<<<256, 256>>>(W1, W2, W3, W4, W5);
    int nb = (nNodes + TN - 1) / TN;
    node_block_kernel<<<nb, THREADS, SMEM_BYTES>>>(A, B, out, nNodes);
}